// round 14
// baseline (speedup 1.0000x reference)
#include <cuda_runtime.h>
#include <cuda_fp16.h>
#include <cstdint>
#include <cstddef>

#define Bsz  512
#define S3v  512
#define Cd   128
#define Mrows (Bsz * S3v)
#define EPSL 1e-5f
#define LDAh 136   // halves per staged row (272B, 16B aligned)

// ---------------- device scratch ----------------
__device__ __half g_xh0[(size_t)Mrows * Cd];
__device__ __half g_xh1[(size_t)Mrows * Cd];
__device__ __half g_Wqkvh[2 * 384 * 128];
__device__ __half g_Woh[2 * 128 * 128];
__device__ __half g_W1h[2 * 512 * 128];
__device__ __half g_W2h[2 * 128 * 512];
__device__ __half g_Wacth[128 * 512];
__device__ float g_s0[Bsz * Cd];
__device__ float g_alpha[Bsz];
__device__ float g_m[Mrows];

// ---------------- helpers ----------------
__device__ __forceinline__ void mmaf16(float* d, const unsigned* a, unsigned b0, unsigned b1) {
    asm("mma.sync.aligned.m16n8k16.row.col.f32.f16.f16.f32 "
        "{%0,%1,%2,%3},{%4,%5,%6,%7},{%8,%9},{%0,%1,%2,%3};"
        : "+f"(d[0]), "+f"(d[1]), "+f"(d[2]), "+f"(d[3])
        : "r"(a[0]), "r"(a[1]), "r"(a[2]), "r"(a[3]), "r"(b0), "r"(b1));
}
__device__ __forceinline__ void ldsm4(unsigned& r0, unsigned& r1, unsigned& r2, unsigned& r3,
                                      uint32_t addr) {
    asm volatile("ldmatrix.sync.aligned.m8n8.x4.shared.b16 {%0,%1,%2,%3}, [%4];"
                 : "=r"(r0), "=r"(r1), "=r"(r2), "=r"(r3) : "r"(addr));
}
__device__ __forceinline__ float shred2(float v) {
    v += __shfl_xor_sync(0xffffffffu, v, 1);
    v += __shfl_xor_sync(0xffffffffu, v, 2);
    return v;
}
__device__ __forceinline__ float shredg(float v) {
    v += __shfl_xor_sync(0xffffffffu, v, 4);
    v += __shfl_xor_sync(0xffffffffu, v, 8);
    v += __shfl_xor_sync(0xffffffffu, v, 16);
    return v;
}
__device__ __forceinline__ void cpa16(void* dst_smem, const void* src) {
    uint32_t d = (uint32_t)__cvta_generic_to_shared(dst_smem);
    asm volatile("cp.async.ca.shared.global [%0], [%1], 16;\n" :: "r"(d), "l"(src));
}
__device__ __forceinline__ void barn(int id, int cnt) {
    asm volatile("bar.sync %0, %1;" :: "r"(id), "r"(cnt) : "memory");
}

// ======================================================================
// K_wtf
// ======================================================================
__global__ void k_wtf(const float* __restrict__ Wqkv, const float* __restrict__ Wo,
                      const float* __restrict__ W1, const float* __restrict__ W2,
                      const float* __restrict__ Wact) {
    int idx = (blockIdx.x * 256 + threadIdx.x) * 4;
    const float* src;
    __half2* dst;
    if (idx < 98304)        { int j = idx;          src = Wqkv + j; dst = (__half2*)(g_Wqkvh + j); }
    else if (idx < 131072)  { int j = idx - 98304;  src = Wo + j;   dst = (__half2*)(g_Woh + j); }
    else if (idx < 262144)  { int j = idx - 131072; src = W1 + j;   dst = (__half2*)(g_W1h + j); }
    else if (idx < 393216)  { int j = idx - 262144; src = W2 + j;   dst = (__half2*)(g_W2h + j); }
    else                    { int j = idx - 393216; src = Wact + j; dst = (__half2*)(g_Wacth + j); }
    float4 v = *(const float4*)src;
    dst[0] = __floats2half2_rn(v.x, v.y);
    dst[1] = __floats2half2_rn(v.z, v.w);
}

// ======================================================================
// K_init
// ======================================================================
__global__ void k_init(const int* __restrict__ xx, const float* __restrict__ ss,
                       const float* __restrict__ Win, const float* __restrict__ b_in) {
    __shared__ float ssm4[4][128];
    __shared__ int nct[4];
    int b = blockIdx.x, tid = threadIdx.x;
    int ph = tid >> 7, c = tid & 127;
    float w0 = Win[c * 5 + 0], w1 = Win[c * 5 + 1], w2 = Win[c * 5 + 2];
    float w3 = Win[c * 5 + 3], w4 = Win[c * 5 + 4];
    float base = (ss[b] * 0.125f) * w4 + b_in[c];
    const int* fp = xx + (size_t)b * 16 * S3v;
    const float inv7 = 1.0f / 7.0f;
    float ssum = 0.f; int ncnt = 0;
    for (int i = 0; i < 128; i++) {
        int p = i * 4 + ph;
        int f = fp[p];
        int ii = p >> 6, jj = (p >> 3) & 7, kk = p & 7;
        float val = base + (float)ii * inv7 * w0 + (float)jj * inv7 * w1 +
                    (float)kk * inv7 * w2 + (float)f * 0.5f * w3;
        g_xh0[((size_t)b * S3v + p) * Cd + c] = __float2half_rn(val);
        if (f != 0) { ssum += val; ncnt++; }
        if (c == 0) g_m[b * S3v + p] = (f != 0) ? 1.0f : 0.0f;
    }
    ssm4[ph][c] = ssum;
    if (c == 0) nct[ph] = ncnt;
    __syncthreads();
    if (tid < 128) {
        float s = ssm4[0][tid] + ssm4[1][tid] + ssm4[2][tid] + ssm4[3][tid];
        g_s0[b * Cd + tid] = s;
    }
    if (tid == 0) {
        int n = nct[0] + nct[1] + nct[2] + nct[3];
        g_alpha[b] = (n > 1) ? 1.0f / (float)(n - 1) : 0.f;
    }
}

// ======================================================================
// K_gnn3: unchanged from R13 (grid=512, 2 CTAs/SM)
// ======================================================================
#define GNN3_DSMEM (34816 * 3 + 6144)
__global__ void __launch_bounds__(256, 2)
k_gnn3(const float* __restrict__ Wr, const float* __restrict__ Wl,
       const float* __restrict__ bl, const float* __restrict__ ln_g,
       const float* __restrict__ ln_b, const float* __restrict__ ss,
       const float* __restrict__ Wsc, const float* __restrict__ bsc,
       float* __restrict__ out) {
    extern __shared__ char smc[];
    __half* W = (__half*)smc;
    __half* Ab0 = (__half*)(smc + 34816);
    float* fx = (float*)(smc + 34816 * 3);
    float* tvs = fx;        float* gsh = fx + 128;
    float* bsh = fx + 256;  float* msk = fx + 384;
    float* sacc = fx + 512; float* redS = fx + 640;
    float* redQ = fx + 896;
    float* ssm = fx + 1152;
    float* pm  = fx + 640;

    int tid = threadIdx.x, wid = tid >> 5, lane = tid & 31;
    int wm = wid >> 1, wn = wid & 1;
    int gid = lane >> 2, tig = lane & 3;

    if (tid < 128) { gsh[tid] = ln_g[tid]; bsh[tid] = ln_b[tid]; }

    uint32_t Wsb = (uint32_t)__cvta_generic_to_shared(W);
    uint32_t Asb = (uint32_t)__cvta_generic_to_shared(Ab0);
    uint32_t aoff[2], boff[4];
#pragma unroll
    for (int mf = 0; mf < 2; mf++)
        aoff[mf] = (uint32_t)(((wm * 32 + mf * 16 + (lane & 15)) * LDAh + ((lane >> 4) << 3)) * 2);
#pragma unroll
    for (int p = 0; p < 4; p++) {
        int n = wn * 64 + p * 16 + (lane & 7) + ((lane >> 4) << 3);
        int koff = ((lane >> 3) & 1) << 3;
        boff[p] = Wsb + (uint32_t)((n * LDAh + koff) * 2);
    }

    __half* XB[2];
    XB[0] = g_xh0; XB[1] = g_xh1;

    int b = blockIdx.x;
    float alpha = g_alpha[b];

    {
        const __half* asrc = g_xh0 + (size_t)b * 512 * Cd;
        for (int u = tid; u < 2048; u += 256) {
            int r = u >> 4, j = u & 15;
            cpa16(Ab0 + r * LDAh + j * 8, asrc + r * Cd + j * 8);
        }
        asm volatile("cp.async.commit_group;\n");
    }
    if (tid < 128) { ssm[tid] = g_s0[b * Cd + tid]; sacc[tid] = 0.f; }
    __syncthreads();

    int bufi = 0;
    for (int l = 0; l < 3; l++) {
        const float* Wr_l = Wr + l * 16384;
        const float* Wl_l = Wl + l * 16384;
        for (int u = tid; u < 2048; u += 256) {
            int n = u >> 4, j = u & 15;
            const float4* wr4 = (const float4*)(Wr_l + n * 128 + j * 8);
            const float4* wl4 = (const float4*)(Wl_l + n * 128 + j * 8);
            float4 a0 = wr4[0], a1 = wr4[1];
            float4 c0 = wl4[0], c1 = wl4[1];
            __half2* d = (__half2*)(W + n * LDAh + j * 8);
            d[0] = __floats2half2_rn(a0.x - alpha * c0.x, a0.y - alpha * c0.y);
            d[1] = __floats2half2_rn(a0.z - alpha * c0.z, a0.w - alpha * c0.w);
            d[2] = __floats2half2_rn(a1.x - alpha * c1.x, a1.y - alpha * c1.y);
            d[3] = __floats2half2_rn(a1.z - alpha * c1.z, a1.w - alpha * c1.w);
        }
        if (tid < 128) {
            const float4* wl4 = (const float4*)(Wl_l + tid * 128);
            float a0 = 0.f, a1 = 0.f, a2 = 0.f, a3 = 0.f;
#pragma unroll
            for (int k4 = 0; k4 < 32; k4 += 4) {
                float4 w0 = wl4[k4], w1 = wl4[k4 + 1], w2 = wl4[k4 + 2], w3 = wl4[k4 + 3];
                a0 += ssm[k4 * 4 + 0] * w0.x + ssm[k4 * 4 + 1] * w0.y + ssm[k4 * 4 + 2] * w0.z + ssm[k4 * 4 + 3] * w0.w;
                a1 += ssm[k4 * 4 + 4] * w1.x + ssm[k4 * 4 + 5] * w1.y + ssm[k4 * 4 + 6] * w1.z + ssm[k4 * 4 + 7] * w1.w;
                a2 += ssm[k4 * 4 + 8] * w2.x + ssm[k4 * 4 + 9] * w2.y + ssm[k4 * 4 + 10] * w2.z + ssm[k4 * 4 + 11] * w2.w;
                a3 += ssm[k4 * 4 + 12] * w3.x + ssm[k4 * 4 + 13] * w3.y + ssm[k4 * 4 + 14] * w3.z + ssm[k4 * 4 + 15] * w3.w;
            }
            tvs[tid] = alpha * (a0 + a1 + a2 + a3) + bl[l * 128 + tid];
        }

        const __half* xin = XB[(l == 1) ? 1 : 0];
        __half* xout = XB[(l == 1) ? 0 : 1];
        int last = (l == 2);

        for (int tt = 0; tt < 4; tt++) {
            int row0 = b * 512 + tt * 128;
            if (tid < 128) msk[tid] = g_m[row0 + tid];
            asm volatile("cp.async.wait_group 0;\n");
            __syncthreads();

            uint32_t ab = Asb + (uint32_t)(bufi * (128 * LDAh * 2));
            float acc[2][8][4];
#pragma unroll
            for (int a0 = 0; a0 < 2; a0++)
#pragma unroll
                for (int a1 = 0; a1 < 8; a1++)
#pragma unroll
                    for (int a2 = 0; a2 < 4; a2++) acc[a0][a1][a2] = 0.f;

#pragma unroll
            for (int ks = 0; ks < 128; ks += 16) {
                unsigned af[2][4], bf[8][2];
#pragma unroll
                for (int mf = 0; mf < 2; mf++)
                    ldsm4(af[mf][0], af[mf][1], af[mf][2], af[mf][3], ab + aoff[mf] + ks * 2);
#pragma unroll
                for (int p = 0; p < 4; p++)
                    ldsm4(bf[p * 2][0], bf[p * 2][1], bf[p * 2 + 1][0], bf[p * 2 + 1][1],
                          boff[p] + ks * 2);
#pragma unroll
                for (int mf = 0; mf < 2; mf++)
#pragma unroll
                    for (int nf = 0; nf < 8; nf++)
                        mmaf16(acc[mf][nf], af[mf], bf[nf][0], bf[nf][1]);
            }

            {
                bool havenext;
                const __half* nsrc = nullptr;
                if (tt < 3) { havenext = true; nsrc = xin + (size_t)(row0 + 128) * Cd; }
                else if (l < 2) {
                    havenext = true;
                    const __half* nin = XB[(l + 1 == 1) ? 1 : 0];
                    nsrc = nin + (size_t)b * 512 * Cd;
                } else havenext = false;
                if (havenext) {
                    __half* dst = Ab0 + (bufi ^ 1) * (128 * LDAh);
                    for (int u = tid; u < 2048; u += 256) {
                        int r = u >> 4, j = u & 15;
                        cpa16(dst + r * LDAh + j * 8, nsrc + r * Cd + j * 8);
                    }
                    asm volatile("cp.async.commit_group;\n");
                }
            }

#pragma unroll
            for (int mf = 0; mf < 2; mf++)
#pragma unroll
                for (int nf = 0; nf < 8; nf++) {
                    int col = wn * 64 + nf * 8 + 2 * tig;
                    float tv0 = tvs[col], tv1 = tvs[col + 1];
#pragma unroll
                    for (int rp = 0; rp < 2; rp++) {
                        acc[mf][nf][rp * 2]     = fmaxf(acc[mf][nf][rp * 2]     + tv0, 0.f);
                        acc[mf][nf][rp * 2 + 1] = fmaxf(acc[mf][nf][rp * 2 + 1] + tv1, 0.f);
                    }
                }
#pragma unroll
            for (int mf = 0; mf < 2; mf++)
#pragma unroll
                for (int rp = 0; rp < 2; rp++) {
                    float s = 0.f, q = 0.f;
#pragma unroll
                    for (int nf = 0; nf < 8; nf++) {
                        float v0 = acc[mf][nf][rp * 2], v1 = acc[mf][nf][rp * 2 + 1];
                        s += v0 + v1; q += v0 * v0 + v1 * v1;
                    }
                    s = shred2(s); q = shred2(q);
                    if (tig == 0) {
                        int r = wm * 32 + mf * 16 + rp * 8 + gid;
                        redS[r * 2 + wn] = s;
                        redQ[r * 2 + wn] = q;
                    }
                }
            barn(1 + wm, 64);
            float csum[8][2];
#pragma unroll
            for (int nf = 0; nf < 8; nf++) { csum[nf][0] = 0.f; csum[nf][1] = 0.f; }
#pragma unroll
            for (int mf = 0; mf < 2; mf++)
#pragma unroll
                for (int rp = 0; rp < 2; rp++) {
                    int r = wm * 32 + mf * 16 + rp * 8 + gid;
                    float s = redS[r * 2] + redS[r * 2 + 1];
                    float q = redQ[r * 2] + redQ[r * 2 + 1];
                    float mu = s * (1.0f / 128.0f);
                    float var = fmaxf(q * (1.0f / 128.0f) - mu * mu, 0.f);
                    float rs = rsqrtf(var + EPSL);
                    float mk = msk[r];
#pragma unroll
                    for (int nf = 0; nf < 8; nf++) {
                        int col = wn * 64 + nf * 8 + 2 * tig;
                        float x0 = (acc[mf][nf][rp * 2]     - mu) * rs * gsh[col] + bsh[col];
                        float x1 = (acc[mf][nf][rp * 2 + 1] - mu) * rs * gsh[col + 1] + bsh[col + 1];
                        *(__half2*)(xout + (size_t)(row0 + r) * Cd + col) = __floats2half2_rn(x0, x1);
                        if (!last) {
                            csum[nf][0] += mk * x0;
                            csum[nf][1] += mk * x1;
                        }
                    }
                }
            if (!last) {
#pragma unroll
                for (int nf = 0; nf < 8; nf++) {
                    csum[nf][0] = shredg(csum[nf][0]);
                    csum[nf][1] = shredg(csum[nf][1]);
                }
                if (gid == 0) {
#pragma unroll
                    for (int nf = 0; nf < 8; nf++) {
                        int col = wn * 64 + nf * 8 + 2 * tig;
                        atomicAdd(&sacc[col], csum[nf][0]);
                        atomicAdd(&sacc[col + 1], csum[nf][1]);
                    }
                }
            }
            bufi ^= 1;
        }
        __syncthreads();
        if (l < 2) {
            if (tid < 128) { ssm[tid] = sacc[tid]; sacc[tid] = 0.f; }
            __syncthreads();
        }
    }

    for (int p = tid; p < 512; p += 256) pm[p] = g_m[b * 512 + p];
    __syncthreads();
    if (tid < 128) {
        int c = tid;
        float aj[8], ak[8];
#pragma unroll
        for (int q = 0; q < 8; q++) { aj[q] = 0.f; ak[q] = 0.f; }
        const __half* xb = g_xh1 + (size_t)b * 512 * Cd + c;
        for (int i = 0; i < 8; i++) {
            float ai = 0.f;
#pragma unroll
            for (int jk = 0; jk < 64; jk++) {
                int p = i * 64 + jk;
                float v = pm[p] * __half2float(xb[(size_t)p * Cd]);
                ai += v; aj[jk >> 3] += v; ak[jk & 7] += v;
            }
            out[((size_t)b * 26 + i) * Cd + c] = ai * 0.015625f;
        }
#pragma unroll
        for (int q = 0; q < 8; q++) {
            out[((size_t)b * 26 + 8 + q) * Cd + c] = aj[q] * 0.015625f;
            out[((size_t)b * 26 + 16 + q) * Cd + c] = ak[q] * 0.015625f;
        }
        out[((size_t)b * 26 + 25) * Cd + c] = fmaxf(ss[b] * Wsc[c] + bsc[c], 0.f);
    }
}

// ======================================================================
// K_tf: 2 batches/CTA (grid 256, 30 rows), ~95.5 KB smem so it can
// co-reside with a k_gnn3 CTA. Single-buffered W. M-tile = 32 rows.
// ======================================================================
#define TF_SMEM 95744
#define QLD 392
__global__ void __launch_bounds__(256, 2)
k_tf(const int* __restrict__ xx,
     const float* __restrict__ bact,
     const float* __restrict__ bqkv, const float* __restrict__ bo,
     const float* __restrict__ b1g, const float* __restrict__ b2g,
     const float* __restrict__ ln1_g, const float* __restrict__ ln1_b,
     const float* __restrict__ ln2_g, const float* __restrict__ ln2_b,
     float* __restrict__ out) {
    extern __shared__ char sm[];
    __half* sW   = (__half*)sm;                     // 128 x LDAh   (34816)
    __half* buf1 = (__half*)(sm + 34816);           // 32 x LDAh    (8704)
    __half* hS   = (__half*)(sm + 43520);           // 32 x LDAh    (8704)
    __half* qkvS = (__half*)(sm + 52224);           // 32 x QLD     (25088)
    float*  aS   = (float*)(sm + 77312);            // 32 x 132     (16896)
    float*  redS = (float*)(sm + 94208);            // [32][4]
    float*  redQ = redS + 128;                      // [32][4]

    int tid = threadIdx.x, wid = tid >> 5, lane = tid & 31;
    int wm = wid & 1, wn = wid >> 1;
    int gid = lane >> 2, tig = lane & 3;
    int row0 = blockIdx.x * 30;
    int b0 = blockIdx.x * 2;

    uint32_t sWB  = (uint32_t)__cvta_generic_to_shared(sW);
    uint32_t bufB = (uint32_t)__cvta_generic_to_shared(buf1);
    uint32_t hSB  = (uint32_t)__cvta_generic_to_shared(hS);
    uint32_t aoff = (uint32_t)(((wm * 16 + (lane & 15)) * LDAh + ((lane >> 4) << 3)) * 2);
    uint32_t boff[2];
#pragma unroll
    for (int p = 0; p < 2; p++) {
        int n = wn * 32 + p * 16 + (lane & 7) + ((lane >> 4) << 3);
        int koff = ((lane >> 3) & 1) << 3;
        boff[p] = (uint32_t)((n * LDAh + koff) * 2);
    }

    const __half* wptr[28]; int wstr[28];
    {
        int i = 0;
        for (int kc = 0; kc < 512; kc += 128) { wptr[i] = g_Wacth + kc; wstr[i++] = 512; }
        for (int l = 0; l < 2; l++) {
            for (int nt = 0; nt < 3; nt++) { wptr[i] = g_Wqkvh + l * 49152 + nt * 16384; wstr[i++] = 128; }
            wptr[i] = g_Woh + l * 16384; wstr[i++] = 128;
            for (int kt = 0; kt < 4; kt++) {
                wptr[i] = g_W1h + l * 65536 + kt * 16384; wstr[i++] = 128;
                wptr[i] = g_W2h + l * 65536 + kt * 128;  wstr[i++] = 512;
            }
        }
    }
    int ipre = 0;
    auto PRE = [&]() {   // single buffer; caller guarantees sW is free
        const __half* src = wptr[ipre];
        int st = wstr[ipre];
        for (int u = tid; u < 2048; u += 256) {
            int n = u >> 4, j = u & 15;
            cpa16(sW + n * LDAh + j * 8, src + (size_t)n * st + j * 8);
        }
        asm volatile("cp.async.commit_group;\n");
        ipre++;
    };
    auto WAITW = [&]() { asm volatile("cp.async.wait_group 0;\n"); };
    auto MML = [&](uint32_t ab, float (&acc)[4][4]) {
#pragma unroll
        for (int ks = 0; ks < 128; ks += 16) {
            unsigned af[4], bf[4][2];
            ldsm4(af[0], af[1], af[2], af[3], ab + aoff + ks * 2);
#pragma unroll
            for (int p = 0; p < 2; p++)
                ldsm4(bf[p * 2][0], bf[p * 2][1], bf[p * 2 + 1][0], bf[p * 2 + 1][1],
                      sWB + boff[p] + ks * 2);
#pragma unroll
            for (int nf = 0; nf < 4; nf++)
                mmaf16(acc[nf], af, bf[nf][0], bf[nf][1]);
        }
    };
    auto ZA = [&](float (&acc)[4][4]) {
#pragma unroll
        for (int a1 = 0; a1 < 4; a1++)
#pragma unroll
            for (int a2 = 0; a2 < 4; a2++) acc[a1][a2] = 0.f;
    };
    auto EPILN = [&](float (&acc)[4][4], const float* bias,
                     const float* lng, const float* lnb, int addRes, int doLN) {
        int gnb = wn * 32 + tig * 2;
#pragma unroll
        for (int rp = 0; rp < 2; rp++) {
            int gm = wm * 16 + rp * 8 + gid;
#pragma unroll
            for (int nf = 0; nf < 4; nf++) {
                int c = gnb + nf * 8;
                float v0 = acc[nf][rp * 2] + bias[c];
                float v1 = acc[nf][rp * 2 + 1] + bias[c + 1];
                if (addRes) { v0 += aS[gm * 132 + c]; v1 += aS[gm * 132 + c + 1]; }
                acc[nf][rp * 2] = v0;
                acc[nf][rp * 2 + 1] = v1;
                aS[gm * 132 + c] = v0;
                aS[gm * 132 + c + 1] = v1;
            }
        }
        if (!doLN) { __syncthreads(); return; }
#pragma unroll
        for (int rp = 0; rp < 2; rp++) {
            float s = 0.f, q = 0.f;
#pragma unroll
            for (int nf = 0; nf < 4; nf++) {
                float v0 = acc[nf][rp * 2], v1 = acc[nf][rp * 2 + 1];
                s += v0 + v1; q += v0 * v0 + v1 * v1;
            }
            s = shred2(s); q = shred2(q);
            if (tig == 0) {
                int r = wm * 16 + rp * 8 + gid;
                redS[r * 4 + wn] = s;
                redQ[r * 4 + wn] = q;
            }
        }
        barn(1 + wm, 128);
#pragma unroll
        for (int rp = 0; rp < 2; rp++) {
            int r = wm * 16 + rp * 8 + gid;
            float s = redS[r * 4] + redS[r * 4 + 1] + redS[r * 4 + 2] + redS[r * 4 + 3];
            float q = redQ[r * 4] + redQ[r * 4 + 1] + redQ[r * 4 + 2] + redQ[r * 4 + 3];
            float mu = s * (1.0f / 128.0f);
            float var = fmaxf(q * (1.0f / 128.0f) - mu * mu, 0.f);
            float rs = rsqrtf(var + EPSL);
#pragma unroll
            for (int nf = 0; nf < 4; nf++) {
                int c = gnb + nf * 8;
                float x0 = (acc[nf][rp * 2] - mu) * rs * lng[c] + lnb[c];
                float x1 = (acc[nf][rp * 2 + 1] - mu) * rs * lng[c + 1] + lnb[c + 1];
                *(__half2*)(hS + r * LDAh + c) = __floats2half2_rn(x0, x1);
            }
        }
        __syncthreads();
    };

    float acc[4][4];

    // ---- stage 0: a = xx @ Wact^T (K=512), then LN1(l0) -> hS ----
    ZA(acc);
    for (int kc = 0; kc < 512; kc += 128) {
        PRE();
        for (int u = tid; u < 1024; u += 256) {
            int r = u >> 5, j = u & 31;
            int gr = row0 + r;
            if (r >= 30) gr = row0;
            int bb = gr / 15, tt = gr - bb * 15;
            int4 v = ((const int4*)(xx + ((size_t)bb * 16 + tt + 1) * 512 + kc))[j];
            __half2* d = (__half2*)(buf1 + r * LDAh + j * 4);
            d[0] = __floats2half2_rn((float)v.x, (float)v.y);
            d[1] = __floats2half2_rn((float)v.z, (float)v.w);
        }
        WAITW();
        __syncthreads();
        MML(bufB, acc);
        __syncthreads();
    }
    EPILN(acc, bact, ln1_g, ln1_b, 0, 1);

    for (int l = 0; l < 2; l++) {
        // ---- qkv: 3 N-tiles ----
        for (int nt = 0; nt < 3; nt++) {
            PRE(); WAITW(); __syncthreads();
            ZA(acc);
            MML(hSB, acc);
            __syncthreads();
            {
                int gnb = wn * 32 + tig * 2;
                const float* bias = bqkv + l * 384 + nt * 128;
#pragma unroll
                for (int rp = 0; rp < 2; rp++) {
                    int gm = wm * 16 + rp * 8 + gid;
#pragma unroll
                    for (int nf = 0; nf < 4; nf++) {
                        int c = gnb + nf * 8;
                        *(__half2*)(qkvS + gm * QLD + nt * 128 + c) =
                            __floats2half2_rn(acc[nf][rp * 2] + bias[c],
                                              acc[nf][rp * 2 + 1] + bias[c + 1]);
                    }
                }
            }
        }
        __syncthreads();
        // ---- attention: 8 (batch,head) tasks over 8 warps ----
        {
            int bloc = wid >> 2, head = wid & 3;
            if (lane < 15) {
                const __half2* qp = (const __half2*)(qkvS + (bloc * 15 + lane) * QLD + head * 32);
                float qr[32];
#pragma unroll
                for (int d2 = 0; d2 < 16; d2++) {
                    float2 f = __half22float2(qp[d2]);
                    qr[d2 * 2] = f.x; qr[d2 * 2 + 1] = f.y;
                }
                float sc[15], mx = -1e30f;
#pragma unroll
                for (int tk = 0; tk < 15; tk++) {
                    const __half2* kp = (const __half2*)(qkvS + (bloc * 15 + tk) * QLD + 128 + head * 32);
                    float a = 0.f;
#pragma unroll
                    for (int d2 = 0; d2 < 16; d2++) {
                        float2 f = __half22float2(kp[d2]);
                        a += qr[d2 * 2] * f.x + qr[d2 * 2 + 1] * f.y;
                    }
                    sc[tk] = a * 0.17677669529663687f;
                    mx = fmaxf(mx, sc[tk]);
                }
                float ssum = 0.f;
#pragma unroll
                for (int tk = 0; tk < 15; tk++) { sc[tk] = expf(sc[tk] - mx); ssum += sc[tk]; }
                float inv = 1.0f / ssum;
                float od[32];
#pragma unroll
                for (int d = 0; d < 32; d++) od[d] = 0.f;
#pragma unroll
                for (int tk = 0; tk < 15; tk++) {
                    float p = sc[tk] * inv;
                    const __half2* vp = (const __half2*)(qkvS + (bloc * 15 + tk) * QLD + 256 + head * 32);
#pragma unroll
                    for (int d2 = 0; d2 < 16; d2++) {
                        float2 f = __half22float2(vp[d2]);
                        od[d2 * 2] += p * f.x; od[d2 * 2 + 1] += p * f.y;
                    }
                }
                __half2* op = (__half2*)(buf1 + (bloc * 15 + lane) * LDAh + head * 32);
#pragma unroll
                for (int d2 = 0; d2 < 16; d2++)
                    op[d2] = __floats2half2_rn(od[d2 * 2], od[d2 * 2 + 1]);
            }
        }
        __syncthreads();
        // ---- Wo + residual + LN2 ----
        PRE(); WAITW(); __syncthreads();
        ZA(acc);
        MML(bufB, acc);
        __syncthreads();
        EPILN(acc, bo + l * 128, ln2_g + l * 128, ln2_b + l * 128, 1, 1);
        // ---- FFN: 4 k-tiles, acc2 accumulates W2 contributions ----
        float acc2[4][4];
        ZA(acc2);
        for (int kt = 0; kt < 4; kt++) {
            PRE(); WAITW(); __syncthreads();
            ZA(acc);
            MML(hSB, acc);
            __syncthreads();
            {
                int gnb = wn * 32 + tig * 2;
                const float* bias = b1g + l * 512 + kt * 128;
#pragma unroll
                for (int rp = 0; rp < 2; rp++) {
                    int gm = wm * 16 + rp * 8 + gid;
#pragma unroll
                    for (int nf = 0; nf < 4; nf++) {
                        int c = gnb + nf * 8;
                        float v0 = fmaxf(acc[nf][rp * 2] + bias[c], 0.f);
                        float v1 = fmaxf(acc[nf][rp * 2 + 1] + bias[c + 1], 0.f);
                        *(__half2*)(buf1 + gm * LDAh + c) = __floats2half2_rn(v0, v1);
                    }
                }
            }
            __syncthreads();
            PRE(); WAITW(); __syncthreads();
            MML(bufB, acc2);
            __syncthreads();
        }
        if (l == 0) {
            EPILN(acc2, b2g, ln1_g + 128, ln1_b + 128, 1, 1);
        } else {
            EPILN(acc2, b2g + 128, nullptr, nullptr, 1, 0);
            if (tid < 128) {
#pragma unroll
                for (int lb = 0; lb < 2; lb++) {
                    float s = 0.f;
#pragma unroll
                    for (int t = 0; t < 15; t++) s += aS[(lb * 15 + t) * 132 + tid];
                    out[((size_t)(b0 + lb) * 26 + 24) * 128 + tid] = s * (1.0f / 15.0f);
                }
            }
        }
    }
}

// ======================================================================
// host launcher — forked streams; k_tf co-resident with k_gnn3
// ======================================================================
extern "C" void kernel_launch(void* const* d_in, const int* in_sizes, int n_in,
                              void* d_out, int out_size) {
    const int*   xx    = (const int*)d_in[0];
    const float* ss    = (const float*)d_in[1];
    const float* Win   = (const float*)d_in[2];
    const float* b_in  = (const float*)d_in[3];
    const float* Wl    = (const float*)d_in[4];
    const float* bl    = (const float*)d_in[5];
    const float* Wr    = (const float*)d_in[6];
    const float* ln_g  = (const float*)d_in[7];
    const float* ln_b  = (const float*)d_in[8];
    const float* Wqkv  = (const float*)d_in[9];
    const float* bqkv  = (const float*)d_in[10];
    const float* Wo    = (const float*)d_in[11];
    const float* bo    = (const float*)d_in[12];
    const float* ln1_g = (const float*)d_in[13];
    const float* ln1_b = (const float*)d_in[14];
    const float* ln2_g = (const float*)d_in[15];
    const float* ln2_b = (const float*)d_in[16];
    const float* W1    = (const float*)d_in[17];
    const float* b1    = (const float*)d_in[18];
    const float* W2    = (const float*)d_in[19];
    const float* b2    = (const float*)d_in[20];
    const float* Wact  = (const float*)d_in[21];
    const float* bact  = (const float*)d_in[22];
    const float* Wsc   = (const float*)d_in[23];
    const float* bsc   = (const float*)d_in[24];
    float* out = (float*)d_out;

    cudaFuncSetAttribute(k_gnn3, cudaFuncAttributeMaxDynamicSharedMemorySize, GNN3_DSMEM);
    cudaFuncSetAttribute(k_tf, cudaFuncAttributeMaxDynamicSharedMemorySize, TF_SMEM);

    cudaStream_t s2;
    cudaEvent_t e0, e1;
    cudaStreamCreateWithFlags(&s2, cudaStreamNonBlocking);
    cudaEventCreateWithFlags(&e0, cudaEventDisableTiming);
    cudaEventCreateWithFlags(&e1, cudaEventDisableTiming);

    // fork: side chain (wtf -> tf)
    cudaEventRecord(e0, 0);
    cudaStreamWaitEvent(s2, e0, 0);
    k_wtf<<<448, 256, 0, s2>>>(Wqkv, Wo, W1, W2, Wact);
    k_tf<<<256, 256, TF_SMEM, s2>>>(xx, bact, bqkv, bo, b1, b2,
                                    ln1_g, ln1_b, ln2_g, ln2_b, out);
    cudaEventRecord(e1, s2);

    // main chain: init -> gnn3
    k_init<<<Bsz, 512>>>(xx, ss, Win, b_in);
    k_gnn3<<<512, 256, GNN3_DSMEM>>>(Wr, Wl, bl, ln_g, ln_b,
                                     ss, Wsc, bsc, out);
    // join
    cudaStreamWaitEvent(0, e1, 0);
}

// round 16
// speedup vs baseline: 1.0156x; 1.0156x over previous
#include <cuda_runtime.h>
#include <cuda_fp16.h>
#include <cstdint>
#include <cstddef>

#define Bsz  512
#define S3v  512
#define Cd   128
#define Mrows (Bsz * S3v)
#define EPSL 1e-5f
#define LDAh 136   // halves per staged row (272B, 16B aligned)

// ---------------- device scratch ----------------
__device__ __half g_xh0[(size_t)Mrows * Cd];
__device__ __half g_xh1[(size_t)Mrows * Cd];
__device__ __half g_Wqkvh[2 * 384 * 128];
__device__ __half g_Woh[2 * 128 * 128];
__device__ __half g_W1h[2 * 512 * 128];
__device__ __half g_W2h[2 * 128 * 512];
__device__ __half g_Wacth[128 * 512];
__device__ float g_s0[Bsz * Cd];
__device__ float g_alpha[Bsz];
__device__ float g_m[Mrows];

// ---------------- helpers ----------------
__device__ __forceinline__ void mmaf16(float* d, const unsigned* a, unsigned b0, unsigned b1) {
    asm("mma.sync.aligned.m16n8k16.row.col.f32.f16.f16.f32 "
        "{%0,%1,%2,%3},{%4,%5,%6,%7},{%8,%9},{%0,%1,%2,%3};"
        : "+f"(d[0]), "+f"(d[1]), "+f"(d[2]), "+f"(d[3])
        : "r"(a[0]), "r"(a[1]), "r"(a[2]), "r"(a[3]), "r"(b0), "r"(b1));
}
__device__ __forceinline__ void ldsm4(unsigned& r0, unsigned& r1, unsigned& r2, unsigned& r3,
                                      uint32_t addr) {
    asm volatile("ldmatrix.sync.aligned.m8n8.x4.shared.b16 {%0,%1,%2,%3}, [%4];"
                 : "=r"(r0), "=r"(r1), "=r"(r2), "=r"(r3) : "r"(addr));
}
__device__ __forceinline__ float shred2(float v) {
    v += __shfl_xor_sync(0xffffffffu, v, 1);
    v += __shfl_xor_sync(0xffffffffu, v, 2);
    return v;
}
__device__ __forceinline__ float shredg(float v) {
    v += __shfl_xor_sync(0xffffffffu, v, 4);
    v += __shfl_xor_sync(0xffffffffu, v, 8);
    v += __shfl_xor_sync(0xffffffffu, v, 16);
    return v;
}
__device__ __forceinline__ void cpa16(void* dst_smem, const void* src) {
    uint32_t d = (uint32_t)__cvta_generic_to_shared(dst_smem);
    asm volatile("cp.async.ca.shared.global [%0], [%1], 16;\n" :: "r"(d), "l"(src));
}
__device__ __forceinline__ void barn(int id, int cnt) {
    asm volatile("bar.sync %0, %1;" :: "r"(id), "r"(cnt) : "memory");
}

// ======================================================================
// K_wtf: transformer weights fp32 -> fp16
// ======================================================================
__global__ void k_wtf(const float* __restrict__ Wqkv, const float* __restrict__ Wo,
                      const float* __restrict__ W1, const float* __restrict__ W2,
                      const float* __restrict__ Wact) {
    int idx = (blockIdx.x * 256 + threadIdx.x) * 4;
    const float* src;
    __half2* dst;
    if (idx < 98304)        { int j = idx;          src = Wqkv + j; dst = (__half2*)(g_Wqkvh + j); }
    else if (idx < 131072)  { int j = idx - 98304;  src = Wo + j;   dst = (__half2*)(g_Woh + j); }
    else if (idx < 262144)  { int j = idx - 131072; src = W1 + j;   dst = (__half2*)(g_W1h + j); }
    else if (idx < 393216)  { int j = idx - 262144; src = W2 + j;   dst = (__half2*)(g_W2h + j); }
    else                    { int j = idx - 393216; src = Wact + j; dst = (__half2*)(g_Wacth + j); }
    float4 v = *(const float4*)src;
    dst[0] = __floats2half2_rn(v.x, v.y);
    dst[1] = __floats2half2_rn(v.z, v.w);
}

// ======================================================================
// K_init
// ======================================================================
__global__ void k_init(const int* __restrict__ xx, const float* __restrict__ ss,
                       const float* __restrict__ Win, const float* __restrict__ b_in) {
    __shared__ float ssm4[4][128];
    __shared__ int nct[4];
    int b = blockIdx.x, tid = threadIdx.x;
    int ph = tid >> 7, c = tid & 127;
    float w0 = Win[c * 5 + 0], w1 = Win[c * 5 + 1], w2 = Win[c * 5 + 2];
    float w3 = Win[c * 5 + 3], w4 = Win[c * 5 + 4];
    float base = (ss[b] * 0.125f) * w4 + b_in[c];
    const int* fp = xx + (size_t)b * 16 * S3v;
    const float inv7 = 1.0f / 7.0f;
    float ssum = 0.f; int ncnt = 0;
    for (int i = 0; i < 128; i++) {
        int p = i * 4 + ph;
        int f = fp[p];
        int ii = p >> 6, jj = (p >> 3) & 7, kk = p & 7;
        float val = base + (float)ii * inv7 * w0 + (float)jj * inv7 * w1 +
                    (float)kk * inv7 * w2 + (float)f * 0.5f * w3;
        g_xh0[((size_t)b * S3v + p) * Cd + c] = __float2half_rn(val);
        if (f != 0) { ssum += val; ncnt++; }
        if (c == 0) g_m[b * S3v + p] = (f != 0) ? 1.0f : 0.0f;
    }
    ssm4[ph][c] = ssum;
    if (c == 0) nct[ph] = ncnt;
    __syncthreads();
    if (tid < 128) {
        float s = ssm4[0][tid] + ssm4[1][tid] + ssm4[2][tid] + ssm4[3][tid];
        g_s0[b * Cd + tid] = s;
    }
    if (tid == 0) {
        int n = nct[0] + nct[1] + nct[2] + nct[3];
        g_alpha[b] = (n > 1) ? 1.0f / (float)(n - 1) : 0.f;
    }
}

// ======================================================================
// K_gnn3: unchanged (grid=512, 2 CTAs/SM)
// ======================================================================
#define GNN3_DSMEM (34816 * 3 + 6144)
__global__ void __launch_bounds__(256, 2)
k_gnn3(const float* __restrict__ Wr, const float* __restrict__ Wl,
       const float* __restrict__ bl, const float* __restrict__ ln_g,
       const float* __restrict__ ln_b, const float* __restrict__ ss,
       const float* __restrict__ Wsc, const float* __restrict__ bsc,
       float* __restrict__ out) {
    extern __shared__ char smc[];
    __half* W = (__half*)smc;
    __half* Ab0 = (__half*)(smc + 34816);
    float* fx = (float*)(smc + 34816 * 3);
    float* tvs = fx;        float* gsh = fx + 128;
    float* bsh = fx + 256;  float* msk = fx + 384;
    float* sacc = fx + 512; float* redS = fx + 640;
    float* redQ = fx + 896;
    float* ssm = fx + 1152;
    float* pm  = fx + 640;

    int tid = threadIdx.x, wid = tid >> 5, lane = tid & 31;
    int wm = wid >> 1, wn = wid & 1;
    int gid = lane >> 2, tig = lane & 3;

    if (tid < 128) { gsh[tid] = ln_g[tid]; bsh[tid] = ln_b[tid]; }

    uint32_t Wsb = (uint32_t)__cvta_generic_to_shared(W);
    uint32_t Asb = (uint32_t)__cvta_generic_to_shared(Ab0);
    uint32_t aoff[2], boff[4];
#pragma unroll
    for (int mf = 0; mf < 2; mf++)
        aoff[mf] = (uint32_t)(((wm * 32 + mf * 16 + (lane & 15)) * LDAh + ((lane >> 4) << 3)) * 2);
#pragma unroll
    for (int p = 0; p < 4; p++) {
        int n = wn * 64 + p * 16 + (lane & 7) + ((lane >> 4) << 3);
        int koff = ((lane >> 3) & 1) << 3;
        boff[p] = Wsb + (uint32_t)((n * LDAh + koff) * 2);
    }

    __half* XB[2];
    XB[0] = g_xh0; XB[1] = g_xh1;

    int b = blockIdx.x;
    float alpha = g_alpha[b];

    {
        const __half* asrc = g_xh0 + (size_t)b * 512 * Cd;
        for (int u = tid; u < 2048; u += 256) {
            int r = u >> 4, j = u & 15;
            cpa16(Ab0 + r * LDAh + j * 8, asrc + r * Cd + j * 8);
        }
        asm volatile("cp.async.commit_group;\n");
    }
    if (tid < 128) { ssm[tid] = g_s0[b * Cd + tid]; sacc[tid] = 0.f; }
    __syncthreads();

    int bufi = 0;
    for (int l = 0; l < 3; l++) {
        const float* Wr_l = Wr + l * 16384;
        const float* Wl_l = Wl + l * 16384;
        for (int u = tid; u < 2048; u += 256) {
            int n = u >> 4, j = u & 15;
            const float4* wr4 = (const float4*)(Wr_l + n * 128 + j * 8);
            const float4* wl4 = (const float4*)(Wl_l + n * 128 + j * 8);
            float4 a0 = wr4[0], a1 = wr4[1];
            float4 c0 = wl4[0], c1 = wl4[1];
            __half2* d = (__half2*)(W + n * LDAh + j * 8);
            d[0] = __floats2half2_rn(a0.x - alpha * c0.x, a0.y - alpha * c0.y);
            d[1] = __floats2half2_rn(a0.z - alpha * c0.z, a0.w - alpha * c0.w);
            d[2] = __floats2half2_rn(a1.x - alpha * c1.x, a1.y - alpha * c1.y);
            d[3] = __floats2half2_rn(a1.z - alpha * c1.z, a1.w - alpha * c1.w);
        }
        if (tid < 128) {
            const float4* wl4 = (const float4*)(Wl_l + tid * 128);
            float a0 = 0.f, a1 = 0.f, a2 = 0.f, a3 = 0.f;
#pragma unroll
            for (int k4 = 0; k4 < 32; k4 += 4) {
                float4 w0 = wl4[k4], w1 = wl4[k4 + 1], w2 = wl4[k4 + 2], w3 = wl4[k4 + 3];
                a0 += ssm[k4 * 4 + 0] * w0.x + ssm[k4 * 4 + 1] * w0.y + ssm[k4 * 4 + 2] * w0.z + ssm[k4 * 4 + 3] * w0.w;
                a1 += ssm[k4 * 4 + 4] * w1.x + ssm[k4 * 4 + 5] * w1.y + ssm[k4 * 4 + 6] * w1.z + ssm[k4 * 4 + 7] * w1.w;
                a2 += ssm[k4 * 4 + 8] * w2.x + ssm[k4 * 4 + 9] * w2.y + ssm[k4 * 4 + 10] * w2.z + ssm[k4 * 4 + 11] * w2.w;
                a3 += ssm[k4 * 4 + 12] * w3.x + ssm[k4 * 4 + 13] * w3.y + ssm[k4 * 4 + 14] * w3.z + ssm[k4 * 4 + 15] * w3.w;
            }
            tvs[tid] = alpha * (a0 + a1 + a2 + a3) + bl[l * 128 + tid];
        }

        const __half* xin = XB[(l == 1) ? 1 : 0];
        __half* xout = XB[(l == 1) ? 0 : 1];
        int last = (l == 2);

        for (int tt = 0; tt < 4; tt++) {
            int row0 = b * 512 + tt * 128;
            if (tid < 128) msk[tid] = g_m[row0 + tid];
            asm volatile("cp.async.wait_group 0;\n");
            __syncthreads();

            uint32_t ab = Asb + (uint32_t)(bufi * (128 * LDAh * 2));
            float acc[2][8][4];
#pragma unroll
            for (int a0 = 0; a0 < 2; a0++)
#pragma unroll
                for (int a1 = 0; a1 < 8; a1++)
#pragma unroll
                    for (int a2 = 0; a2 < 4; a2++) acc[a0][a1][a2] = 0.f;

#pragma unroll
            for (int ks = 0; ks < 128; ks += 16) {
                unsigned af[2][4], bf[8][2];
#pragma unroll
                for (int mf = 0; mf < 2; mf++)
                    ldsm4(af[mf][0], af[mf][1], af[mf][2], af[mf][3], ab + aoff[mf] + ks * 2);
#pragma unroll
                for (int p = 0; p < 4; p++)
                    ldsm4(bf[p * 2][0], bf[p * 2][1], bf[p * 2 + 1][0], bf[p * 2 + 1][1],
                          boff[p] + ks * 2);
#pragma unroll
                for (int mf = 0; mf < 2; mf++)
#pragma unroll
                    for (int nf = 0; nf < 8; nf++)
                        mmaf16(acc[mf][nf], af[mf], bf[nf][0], bf[nf][1]);
            }

            {
                bool havenext;
                const __half* nsrc = nullptr;
                if (tt < 3) { havenext = true; nsrc = xin + (size_t)(row0 + 128) * Cd; }
                else if (l < 2) {
                    havenext = true;
                    const __half* nin = XB[(l + 1 == 1) ? 1 : 0];
                    nsrc = nin + (size_t)b * 512 * Cd;
                } else havenext = false;
                if (havenext) {
                    __half* dst = Ab0 + (bufi ^ 1) * (128 * LDAh);
                    for (int u = tid; u < 2048; u += 256) {
                        int r = u >> 4, j = u & 15;
                        cpa16(dst + r * LDAh + j * 8, nsrc + r * Cd + j * 8);
                    }
                    asm volatile("cp.async.commit_group;\n");
                }
            }

#pragma unroll
            for (int mf = 0; mf < 2; mf++)
#pragma unroll
                for (int nf = 0; nf < 8; nf++) {
                    int col = wn * 64 + nf * 8 + 2 * tig;
                    float tv0 = tvs[col], tv1 = tvs[col + 1];
#pragma unroll
                    for (int rp = 0; rp < 2; rp++) {
                        acc[mf][nf][rp * 2]     = fmaxf(acc[mf][nf][rp * 2]     + tv0, 0.f);
                        acc[mf][nf][rp * 2 + 1] = fmaxf(acc[mf][nf][rp * 2 + 1] + tv1, 0.f);
                    }
                }
#pragma unroll
            for (int mf = 0; mf < 2; mf++)
#pragma unroll
                for (int rp = 0; rp < 2; rp++) {
                    float s = 0.f, q = 0.f;
#pragma unroll
                    for (int nf = 0; nf < 8; nf++) {
                        float v0 = acc[mf][nf][rp * 2], v1 = acc[mf][nf][rp * 2 + 1];
                        s += v0 + v1; q += v0 * v0 + v1 * v1;
                    }
                    s = shred2(s); q = shred2(q);
                    if (tig == 0) {
                        int r = wm * 32 + mf * 16 + rp * 8 + gid;
                        redS[r * 2 + wn] = s;
                        redQ[r * 2 + wn] = q;
                    }
                }
            barn(1 + wm, 64);
            float csum[8][2];
#pragma unroll
            for (int nf = 0; nf < 8; nf++) { csum[nf][0] = 0.f; csum[nf][1] = 0.f; }
#pragma unroll
            for (int mf = 0; mf < 2; mf++)
#pragma unroll
                for (int rp = 0; rp < 2; rp++) {
                    int r = wm * 32 + mf * 16 + rp * 8 + gid;
                    float s = redS[r * 2] + redS[r * 2 + 1];
                    float q = redQ[r * 2] + redQ[r * 2 + 1];
                    float mu = s * (1.0f / 128.0f);
                    float var = fmaxf(q * (1.0f / 128.0f) - mu * mu, 0.f);
                    float rs = rsqrtf(var + EPSL);
                    float mk = msk[r];
#pragma unroll
                    for (int nf = 0; nf < 8; nf++) {
                        int col = wn * 64 + nf * 8 + 2 * tig;
                        float x0 = (acc[mf][nf][rp * 2]     - mu) * rs * gsh[col] + bsh[col];
                        float x1 = (acc[mf][nf][rp * 2 + 1] - mu) * rs * gsh[col + 1] + bsh[col + 1];
                        *(__half2*)(xout + (size_t)(row0 + r) * Cd + col) = __floats2half2_rn(x0, x1);
                        if (!last) {
                            csum[nf][0] += mk * x0;
                            csum[nf][1] += mk * x1;
                        }
                    }
                }
            if (!last) {
#pragma unroll
                for (int nf = 0; nf < 8; nf++) {
                    csum[nf][0] = shredg(csum[nf][0]);
                    csum[nf][1] = shredg(csum[nf][1]);
                }
                if (gid == 0) {
#pragma unroll
                    for (int nf = 0; nf < 8; nf++) {
                        int col = wn * 64 + nf * 8 + 2 * tig;
                        atomicAdd(&sacc[col], csum[nf][0]);
                        atomicAdd(&sacc[col + 1], csum[nf][1]);
                    }
                }
            }
            bufi ^= 1;
        }
        __syncthreads();
        if (l < 2) {
            if (tid < 128) { ssm[tid] = sacc[tid]; sacc[tid] = 0.f; }
            __syncthreads();
        }
    }

    for (int p = tid; p < 512; p += 256) pm[p] = g_m[b * 512 + p];
    __syncthreads();
    if (tid < 128) {
        int c = tid;
        float aj[8], ak[8];
#pragma unroll
        for (int q = 0; q < 8; q++) { aj[q] = 0.f; ak[q] = 0.f; }
        const __half* xb = g_xh1 + (size_t)b * 512 * Cd + c;
        for (int i = 0; i < 8; i++) {
            float ai = 0.f;
#pragma unroll
            for (int jk = 0; jk < 64; jk++) {
                int p = i * 64 + jk;
                float v = pm[p] * __half2float(xb[(size_t)p * Cd]);
                ai += v; aj[jk >> 3] += v; ak[jk & 7] += v;
            }
            out[((size_t)b * 26 + i) * Cd + c] = ai * 0.015625f;
        }
#pragma unroll
        for (int q = 0; q < 8; q++) {
            out[((size_t)b * 26 + 8 + q) * Cd + c] = aj[q] * 0.015625f;
            out[((size_t)b * 26 + 16 + q) * Cd + c] = ak[q] * 0.015625f;
        }
        out[((size_t)b * 26 + 25) * Cd + c] = fmaxf(ss[b] * Wsc[c] + bsc[c], 0.f);
    }
}

// ======================================================================
// K_tf: fused transformer (60 rows/CTA, double-buffered W)
// ======================================================================
#define TF_SMEM 190976
#define QLD 392
__global__ void __launch_bounds__(256, 1)
k_tf(const int* __restrict__ xx,
     const float* __restrict__ bact,
     const float* __restrict__ bqkv, const float* __restrict__ bo,
     const float* __restrict__ b1g, const float* __restrict__ b2g,
     const float* __restrict__ ln1_g, const float* __restrict__ ln1_b,
     const float* __restrict__ ln2_g, const float* __restrict__ ln2_b,
     float* __restrict__ out) {
    extern __shared__ char sm[];
    __half* sW0  = (__half*)sm;
    __half* sW1  = (__half*)(sm + 34816);
    __half* buf1 = (__half*)(sm + 69632);
    __half* hS   = (__half*)(sm + 87040);
    __half* qkvS = (__half*)(sm + 104448);
    float*  aS   = (float*)(sm + 154624);
    float*  redS = (float*)(sm + 188416);
    float*  redQ = redS + 256;

    int tid = threadIdx.x, wid = tid >> 5, lane = tid & 31;
    int wm = wid & 1, wn = wid >> 1;
    int gid = lane >> 2, tig = lane & 3;
    int row0 = blockIdx.x * 60;
    int b0 = blockIdx.x * 4;

    uint32_t sWb[2] = { (uint32_t)__cvta_generic_to_shared(sW0),
                        (uint32_t)__cvta_generic_to_shared(sW1) };
    uint32_t bufB = (uint32_t)__cvta_generic_to_shared(buf1);
    uint32_t hSB  = (uint32_t)__cvta_generic_to_shared(hS);
    uint32_t aoff[2], boff[2];
#pragma unroll
    for (int mf = 0; mf < 2; mf++)
        aoff[mf] = (uint32_t)(((wm * 32 + mf * 16 + (lane & 15)) * LDAh + ((lane >> 4) << 3)) * 2);
#pragma unroll
    for (int p = 0; p < 2; p++) {
        int n = wn * 32 + p * 16 + (lane & 7) + ((lane >> 4) << 3);
        int koff = ((lane >> 3) & 1) << 3;
        boff[p] = (uint32_t)((n * LDAh + koff) * 2);
    }

    const __half* wptr[28]; int wstr[28];
    {
        int i = 0;
        for (int kc = 0; kc < 512; kc += 128) { wptr[i] = g_Wacth + kc; wstr[i++] = 512; }
        for (int l = 0; l < 2; l++) {
            for (int nt = 0; nt < 3; nt++) { wptr[i] = g_Wqkvh + l * 49152 + nt * 16384; wstr[i++] = 128; }
            wptr[i] = g_Woh + l * 16384; wstr[i++] = 128;
            for (int kt = 0; kt < 4; kt++) {
                wptr[i] = g_W1h + l * 65536 + kt * 16384; wstr[i++] = 128;
                wptr[i] = g_W2h + l * 65536 + kt * 128;  wstr[i++] = 512;
            }
        }
    }
    int ipre = 0, iuse = 0;
    auto PRE = [&]() {
        if (ipre >= 28) return;
        const __half* src = wptr[ipre];
        int st = wstr[ipre];
        __half* dst = (ipre & 1) ? sW1 : sW0;
        for (int u = tid; u < 2048; u += 256) {
            int n = u >> 4, j = u & 15;
            cpa16(dst + n * LDAh + j * 8, src + (size_t)n * st + j * 8);
        }
        asm volatile("cp.async.commit_group;\n");
        ipre++;
    };
    auto WAITW = [&]() {
        if (ipre - iuse > 1) asm volatile("cp.async.wait_group 1;\n");
        else                 asm volatile("cp.async.wait_group 0;\n");
    };
    auto MML = [&](uint32_t ab, float (&acc)[2][4][4]) {
        uint32_t wb = sWb[iuse & 1];
#pragma unroll
        for (int ks = 0; ks < 128; ks += 16) {
            unsigned af[2][4], bf[4][2];
#pragma unroll
            for (int mf = 0; mf < 2; mf++)
                ldsm4(af[mf][0], af[mf][1], af[mf][2], af[mf][3], ab + aoff[mf] + ks * 2);
#pragma unroll
            for (int p = 0; p < 2; p++)
                ldsm4(bf[p * 2][0], bf[p * 2][1], bf[p * 2 + 1][0], bf[p * 2 + 1][1],
                      wb + boff[p] + ks * 2);
#pragma unroll
            for (int mf = 0; mf < 2; mf++)
#pragma unroll
                for (int nf = 0; nf < 4; nf++)
                    mmaf16(acc[mf][nf], af[mf], bf[nf][0], bf[nf][1]);
        }
        iuse++;
    };
    auto ZA = [&](float (&acc)[2][4][4]) {
#pragma unroll
        for (int a0 = 0; a0 < 2; a0++)
#pragma unroll
            for (int a1 = 0; a1 < 4; a1++)
#pragma unroll
                for (int a2 = 0; a2 < 4; a2++) acc[a0][a1][a2] = 0.f;
    };
    auto EPILN = [&](float (&acc)[2][4][4], const float* bias,
                     const float* lng, const float* lnb, int addRes, int doLN) {
        int gnb = wn * 32 + tig * 2;
#pragma unroll
        for (int mf = 0; mf < 2; mf++)
#pragma unroll
            for (int rp = 0; rp < 2; rp++) {
                int gm = wm * 32 + mf * 16 + rp * 8 + gid;
#pragma unroll
                for (int nf = 0; nf < 4; nf++) {
                    int c = gnb + nf * 8;
                    float v0 = acc[mf][nf][rp * 2] + bias[c];
                    float v1 = acc[mf][nf][rp * 2 + 1] + bias[c + 1];
                    if (addRes) { v0 += aS[gm * 132 + c]; v1 += aS[gm * 132 + c + 1]; }
                    acc[mf][nf][rp * 2] = v0;
                    acc[mf][nf][rp * 2 + 1] = v1;
                    aS[gm * 132 + c] = v0;
                    aS[gm * 132 + c + 1] = v1;
                }
            }
        if (!doLN) { __syncthreads(); return; }
#pragma unroll
        for (int mf = 0; mf < 2; mf++)
#pragma unroll
            for (int rp = 0; rp < 2; rp++) {
                float s = 0.f, q = 0.f;
#pragma unroll
                for (int nf = 0; nf < 4; nf++) {
                    float v0 = acc[mf][nf][rp * 2], v1 = acc[mf][nf][rp * 2 + 1];
                    s += v0 + v1; q += v0 * v0 + v1 * v1;
                }
                s = shred2(s); q = shred2(q);
                if (tig == 0) {
                    int r = wm * 32 + mf * 16 + rp * 8 + gid;
                    redS[r * 4 + wn] = s;
                    redQ[r * 4 + wn] = q;
                }
            }
        barn(1 + wm, 128);
#pragma unroll
        for (int mf = 0; mf < 2; mf++)
#pragma unroll
            for (int rp = 0; rp < 2; rp++) {
                int r = wm * 32 + mf * 16 + rp * 8 + gid;
                float s = redS[r * 4] + redS[r * 4 + 1] + redS[r * 4 + 2] + redS[r * 4 + 3];
                float q = redQ[r * 4] + redQ[r * 4 + 1] + redQ[r * 4 + 2] + redQ[r * 4 + 3];
                float mu = s * (1.0f / 128.0f);
                float var = fmaxf(q * (1.0f / 128.0f) - mu * mu, 0.f);
                float rs = rsqrtf(var + EPSL);
#pragma unroll
                for (int nf = 0; nf < 4; nf++) {
                    int c = gnb + nf * 8;
                    float x0 = (acc[mf][nf][rp * 2] - mu) * rs * lng[c] + lnb[c];
                    float x1 = (acc[mf][nf][rp * 2 + 1] - mu) * rs * lng[c + 1] + lnb[c + 1];
                    *(__half2*)(hS + r * LDAh + c) = __floats2half2_rn(x0, x1);
                }
            }
        __syncthreads();
    };

    float acc[2][4][4];

    PRE();
    ZA(acc);
    for (int kc = 0; kc < 512; kc += 128) {
        PRE();
        for (int u = tid; u < 2048; u += 256) {
            int r = u >> 5, j = u & 31;
            int gr = row0 + r;
            if (r >= 60) gr = row0;
            int bb = gr / 15, tt = gr - bb * 15;
            int4 v = ((const int4*)(xx + ((size_t)bb * 16 + tt + 1) * 512 + kc))[j];
            __half2* d = (__half2*)(buf1 + r * LDAh + j * 4);
            d[0] = __floats2half2_rn((float)v.x, (float)v.y);
            d[1] = __floats2half2_rn((float)v.z, (float)v.w);
        }
        WAITW();
        __syncthreads();
        MML(bufB, acc);
        __syncthreads();
    }
    EPILN(acc, bact, ln1_g, ln1_b, 0, 1);

    for (int l = 0; l < 2; l++) {
        for (int nt = 0; nt < 3; nt++) {
            PRE(); WAITW(); __syncthreads();
            ZA(acc);
            MML(hSB, acc);
            __syncthreads();
            {
                int gnb = wn * 32 + tig * 2;
                const float* bias = bqkv + l * 384 + nt * 128;
#pragma unroll
                for (int mf = 0; mf < 2; mf++)
#pragma unroll
                    for (int rp = 0; rp < 2; rp++) {
                        int gm = wm * 32 + mf * 16 + rp * 8 + gid;
#pragma unroll
                        for (int nf = 0; nf < 4; nf++) {
                            int c = gnb + nf * 8;
                            *(__half2*)(qkvS + gm * QLD + nt * 128 + c) =
                                __floats2half2_rn(acc[mf][nf][rp * 2] + bias[c],
                                                  acc[mf][nf][rp * 2 + 1] + bias[c + 1]);
                        }
                    }
            }
        }
        __syncthreads();
        for (int task = wid; task < 16; task += 8) {
            int bloc = task >> 2, head = task & 3;
            if (lane < 15) {
                const __half2* qp = (const __half2*)(qkvS + (bloc * 15 + lane) * QLD + head * 32);
                float qr[32];
#pragma unroll
                for (int d2 = 0; d2 < 16; d2++) {
                    float2 f = __half22float2(qp[d2]);
                    qr[d2 * 2] = f.x; qr[d2 * 2 + 1] = f.y;
                }
                float sc[15], mx = -1e30f;
#pragma unroll
                for (int tk = 0; tk < 15; tk++) {
                    const __half2* kp = (const __half2*)(qkvS + (bloc * 15 + tk) * QLD + 128 + head * 32);
                    float a = 0.f;
#pragma unroll
                    for (int d2 = 0; d2 < 16; d2++) {
                        float2 f = __half22float2(kp[d2]);
                        a += qr[d2 * 2] * f.x + qr[d2 * 2 + 1] * f.y;
                    }
                    sc[tk] = a * 0.17677669529663687f;
                    mx = fmaxf(mx, sc[tk]);
                }
                float ssum = 0.f;
#pragma unroll
                for (int tk = 0; tk < 15; tk++) { sc[tk] = expf(sc[tk] - mx); ssum += sc[tk]; }
                float inv = 1.0f / ssum;
                float od[32];
#pragma unroll
                for (int d = 0; d < 32; d++) od[d] = 0.f;
#pragma unroll
                for (int tk = 0; tk < 15; tk++) {
                    float p = sc[tk] * inv;
                    const __half2* vp = (const __half2*)(qkvS + (bloc * 15 + tk) * QLD + 256 + head * 32);
#pragma unroll
                    for (int d2 = 0; d2 < 16; d2++) {
                        float2 f = __half22float2(vp[d2]);
                        od[d2 * 2] += p * f.x; od[d2 * 2 + 1] += p * f.y;
                    }
                }
                __half2* op = (__half2*)(buf1 + (bloc * 15 + lane) * LDAh + head * 32);
#pragma unroll
                for (int d2 = 0; d2 < 16; d2++)
                    op[d2] = __floats2half2_rn(od[d2 * 2], od[d2 * 2 + 1]);
            }
        }
        __syncthreads();
        PRE(); WAITW(); __syncthreads();
        ZA(acc);
        MML(bufB, acc);
        __syncthreads();
        EPILN(acc, bo + l * 128, ln2_g + l * 128, ln2_b + l * 128, 1, 1);
        float acc2[2][4][4];
        ZA(acc2);
        for (int kt = 0; kt < 4; kt++) {
            PRE(); WAITW(); __syncthreads();
            ZA(acc);
            MML(hSB, acc);
            __syncthreads();
            {
                int gnb = wn * 32 + tig * 2;
                const float* bias = b1g + l * 512 + kt * 128;
#pragma unroll
                for (int mf = 0; mf < 2; mf++)
#pragma unroll
                    for (int rp = 0; rp < 2; rp++) {
                        int gm = wm * 32 + mf * 16 + rp * 8 + gid;
#pragma unroll
                        for (int nf = 0; nf < 4; nf++) {
                            int c = gnb + nf * 8;
                            float v0 = fmaxf(acc[mf][nf][rp * 2] + bias[c], 0.f);
                            float v1 = fmaxf(acc[mf][nf][rp * 2 + 1] + bias[c + 1], 0.f);
                            *(__half2*)(buf1 + gm * LDAh + c) = __floats2half2_rn(v0, v1);
                        }
                    }
            }
            __syncthreads();
            PRE(); WAITW(); __syncthreads();
            MML(bufB, acc2);
            __syncthreads();
        }
        if (l == 0) {
            EPILN(acc2, b2g, ln1_g + 128, ln1_b + 128, 1, 1);
        } else {
            EPILN(acc2, b2g + 128, nullptr, nullptr, 1, 0);
            if (tid < 128) {
#pragma unroll
                for (int lb = 0; lb < 4; lb++) {
                    float s = 0.f;
#pragma unroll
                    for (int t = 0; t < 15; t++) s += aS[(lb * 15 + t) * 132 + tid];
                    out[((size_t)(b0 + lb) * 26 + 24) * 128 + tid] = s * (1.0f / 15.0f);
                }
            }
        }
    }
}

// ======================================================================
// host launcher — R13 resource pattern (no priority streams); tf gated
// behind init so gnn3 is enqueued & ready before tf becomes runnable.
// ======================================================================
extern "C" void kernel_launch(void* const* d_in, const int* in_sizes, int n_in,
                              void* d_out, int out_size) {
    const int*   xx    = (const int*)d_in[0];
    const float* ss    = (const float*)d_in[1];
    const float* Win   = (const float*)d_in[2];
    const float* b_in  = (const float*)d_in[3];
    const float* Wl    = (const float*)d_in[4];
    const float* bl    = (const float*)d_in[5];
    const float* Wr    = (const float*)d_in[6];
    const float* ln_g  = (const float*)d_in[7];
    const float* ln_b  = (const float*)d_in[8];
    const float* Wqkv  = (const float*)d_in[9];
    const float* bqkv  = (const float*)d_in[10];
    const float* Wo    = (const float*)d_in[11];
    const float* bo    = (const float*)d_in[12];
    const float* ln1_g = (const float*)d_in[13];
    const float* ln1_b = (const float*)d_in[14];
    const float* ln2_g = (const float*)d_in[15];
    const float* ln2_b = (const float*)d_in[16];
    const float* W1    = (const float*)d_in[17];
    const float* b1    = (const float*)d_in[18];
    const float* W2    = (const float*)d_in[19];
    const float* b2    = (const float*)d_in[20];
    const float* Wact  = (const float*)d_in[21];
    const float* bact  = (const float*)d_in[22];
    const float* Wsc   = (const float*)d_in[23];
    const float* bsc   = (const float*)d_in[24];
    float* out = (float*)d_out;

    cudaFuncSetAttribute(k_gnn3, cudaFuncAttributeMaxDynamicSharedMemorySize, GNN3_DSMEM);
    cudaFuncSetAttribute(k_tf, cudaFuncAttributeMaxDynamicSharedMemorySize, TF_SMEM);

    cudaStream_t s2;
    cudaEvent_t e0, eInit, e1;
    cudaStreamCreateWithFlags(&s2, cudaStreamNonBlocking);
    cudaEventCreateWithFlags(&e0, cudaEventDisableTiming);
    cudaEventCreateWithFlags(&eInit, cudaEventDisableTiming);
    cudaEventCreateWithFlags(&e1, cudaEventDisableTiming);

    // fork: wtf starts immediately on the side stream
    cudaEventRecord(e0, 0);
    cudaStreamWaitEvent(s2, e0, 0);
    k_wtf<<<448, 256, 0, s2>>>(Wqkv, Wo, W1, W2, Wact);

    // main chain: init -> gnn3 (gnn3 enqueued BEFORE tf becomes runnable)
    k_init<<<Bsz, 512>>>(xx, ss, Win, b_in);
    cudaEventRecord(eInit, 0);
    k_gnn3<<<512, 256, GNN3_DSMEM>>>(Wr, Wl, bl, ln_g, ln_b,
                                     ss, Wsc, bsc, out);

    // side chain: tf gated behind init; backfills during gnn3 drain
    cudaStreamWaitEvent(s2, eInit, 0);
    k_tf<<<128, 256, TF_SMEM, s2>>>(xx, bact, bqkv, bo, b1, b2,
                                    ln1_g, ln1_b, ln2_g, ln2_b, out);
    cudaEventRecord(e1, s2);

    // join
    cudaStreamWaitEvent(0, e1, 0);
}